// round 8
// baseline (speedup 1.0000x reference)
#include <cuda_runtime.h>
#include <cuda_fp16.h>
#include <math.h>
#include <stdint.h>

// Problem constants
#define Bq 2048
#define Iq 1024
#define Hq 2048
#define Cq 1000
#define Sq 8
#define N1 (Sq * 2 * Hq)   // 32768
#define TOPKq 256
#define EPSq 1e-8f

// ---------------- scratch (device globals; no allocation allowed) ----------
__device__ float g_act[(size_t)Bq * N1];
__device__ float g_norm[Bq * Sq];
__device__ float g_cphi[Sq * Hq];
__device__ float g_sphi[Sq * Hq];
__device__ float g_supr[Bq * Hq];
__device__ float g_supi[Bq * Hq];

// fp16 hi/lo splits (both operands) for near-fp32 emulation
__device__ __align__(16) __half g_xhi[(size_t)Bq * Iq];
__device__ __align__(16) __half g_xlo[(size_t)Bq * Iq];
__device__ __align__(16) __half g_whi[(size_t)N1 * Iq];
__device__ __align__(16) __half g_wlo[(size_t)N1 * Iq];
__device__ __align__(16) __half g_gwhi[(size_t)Hq * Hq];
__device__ __align__(16) __half g_gwlo[(size_t)Hq * Hq];
__device__ __align__(16) __half g_cwhi[(size_t)Cq * Hq];
__device__ __align__(16) __half g_cwlo[(size_t)Cq * Hq];
__device__ __align__(16) __half g_mhi[(size_t)Bq * Hq];
__device__ __align__(16) __half g_mlo[(size_t)Bq * Hq];
__device__ __align__(16) __half g_pbhi[(size_t)Bq * Hq];
__device__ __align__(16) __half g_pblo[(size_t)Bq * Hq];

// ---------------- PTX helpers ----------------------------------------------
__device__ __forceinline__ uint32_t smem_u32(const void* p) {
    uint32_t a;
    asm("{ .reg .u64 t; cvta.to.shared.u64 t, %1; cvt.u32.u64 %0, t; }" : "=r"(a) : "l"(p));
    return a;
}

#define CP16(dst, src, szr) \
    asm volatile("cp.async.cg.shared.global [%0], [%1], 16, %2;" \
                 :: "r"(dst), "l"(src), "r"(szr) : "memory")
#define CP_COMMIT() asm volatile("cp.async.commit_group;" ::: "memory")
#define CP_WAIT1()  asm volatile("cp.async.wait_group 1;" ::: "memory")

#define LDSM_X4(r0, r1, r2, r3, addr) \
    asm volatile("ldmatrix.sync.aligned.m8n8.x4.shared.b16 {%0,%1,%2,%3}, [%4];" \
                 : "=r"(r0), "=r"(r1), "=r"(r2), "=r"(r3) : "r"(addr))

#define MMA16816(d, a, b) \
    asm volatile("mma.sync.aligned.m16n8k16.row.col.f32.f16.f16.f32 " \
                 "{%0,%1,%2,%3}, {%4,%5,%6,%7}, {%8,%9}, {%0,%1,%2,%3};" \
                 : "+f"((d)[0]), "+f"((d)[1]), "+f"((d)[2]), "+f"((d)[3]) \
                 : "r"((a)[0]), "r"((a)[1]), "r"((a)[2]), "r"((a)[3]), \
                   "r"((b)[0]), "r"((b)[1]))

// ---------------- small helpers --------------------------------------------
__global__ void zero_norm_kernel() {
    int i = blockIdx.x * blockDim.x + threadIdx.x;
    if (i < Bq * Sq) g_norm[i] = 0.0f;
}

__global__ void sincos_kernel(const float* __restrict__ phases) {
    int i = blockIdx.x * blockDim.x + threadIdx.x;
    if (i < Sq * Hq) {
        float s, c;
        sincosf(phases[i], &s, &c);
        g_cphi[i] = c;
        g_sphi[i] = s;
    }
}

// fp32 -> fp16 hi/lo split
__global__ __launch_bounds__(256) void split_kernel(
    const float* __restrict__ src, __half* __restrict__ hi,
    __half* __restrict__ lo, int n4)
{
    int i = blockIdx.x * blockDim.x + threadIdx.x;
    if (i >= n4) return;
    float4 v = ((const float4*)src)[i];
    __half h0 = __float2half_rn(v.x);
    __half h1 = __float2half_rn(v.y);
    __half h2 = __float2half_rn(v.z);
    __half h3 = __float2half_rn(v.w);
    __half2 hh0 = {h0, h1}, hh1 = {h2, h3};
    ((__half2*)hi)[i * 2 + 0] = hh0;
    ((__half2*)hi)[i * 2 + 1] = hh1;
    __half2 ll0 = {__float2half_rn(v.x - __half2float(h0)),
                   __float2half_rn(v.y - __half2float(h1))};
    __half2 ll1 = {__float2half_rn(v.z - __half2float(h2)),
                   __float2half_rn(v.w - __half2float(h3))};
    ((__half2*)lo)[i * 2 + 0] = ll0;
    ((__half2*)lo)[i * 2 + 1] = ll1;
}

// ---------------- warp-mma GEMM: fp16 3-term, CTA 128x256, warp 64x64 -------
// 8 warps (2x4). K-step 32, cp.async 3-stage. EPI: 0=gemm1, 1=gate, 2=clf.
#define A_COMP 8192    // 128 rows * 64 B
#define B_COMP 16384   // 256 rows * 64 B
#define STAGE_B (2 * A_COMP + 2 * B_COMP)   // 48 KB
#define GEMM_SMEM (3 * STAGE_B)             // 144 KB

__device__ __forceinline__ void prefetch_tiles(
    uint32_t smb, const __half* __restrict__ Ahi, const __half* __restrict__ Alo,
    const __half* __restrict__ Bhi, const __half* __restrict__ Blo,
    int mBase, int nBase, int kk, int KT, int Nr, int tid)
{
    // A: 128 rows x 64B, 512 chunks per component
#pragma unroll
    for (int l = 0; l < 2; ++l) {
        int idx = tid + l * 256;
        int r = idx >> 2, c = idx & 3;
        uint32_t dst = smb + r * 64 + (((c + (r >> 1)) & 3) << 4);
        size_t ka = (size_t)(mBase + r) * KT + kk + c * 8;
        CP16(dst,          Ahi + ka, 16);
        CP16(dst + A_COMP, Alo + ka, 16);
    }
    // B: 256 rows x 64B, 1024 chunks per component
#pragma unroll
    for (int l = 0; l < 4; ++l) {
        int idx = tid + l * 256;
        int r = idx >> 2, c = idx & 3;
        uint32_t dst = smb + 2 * A_COMP + r * 64 + (((c + (r >> 1)) & 3) << 4);
        size_t kb = (size_t)(nBase + r) * KT + kk + c * 8;
        int bsz = ((nBase + r) < Nr) ? 16 : 0;
        CP16(dst,          Bhi + kb, bsz);
        CP16(dst + B_COMP, Blo + kb, bsz);
    }
}

template <int KT, int EPI>
__global__ __launch_bounds__(256, 1) void mma_gemm_kernel(
    const __half* __restrict__ Ahi, const __half* __restrict__ Alo,
    const __half* __restrict__ Bhi, const __half* __restrict__ Blo,
    const float* __restrict__ biasv, float* __restrict__ outp, int Nr)
{
    extern __shared__ __align__(16) char dynsm[];
    uint32_t smbase = smem_u32(dynsm);

    int tid = threadIdx.x;
    int lane = tid & 31, wid = tid >> 5;
    int wr = wid >> 2, wc = wid & 3;          // 2 x 4 warps, each 64x64
    int mBase = blockIdx.x * 128;
    int nBase = blockIdx.y * 256;

    float acc[4][8][4];
#pragma unroll
    for (int a = 0; a < 4; a++)
#pragma unroll
        for (int b = 0; b < 8; b++)
#pragma unroll
            for (int c = 0; c < 4; c++) acc[a][b][c] = 0.0f;

    const int KSTEPS = KT / 32;
    prefetch_tiles(smbase, Ahi, Alo, Bhi, Blo, mBase, nBase, 0, KT, Nr, tid);
    CP_COMMIT();
    prefetch_tiles(smbase + STAGE_B, Ahi, Alo, Bhi, Blo, mBase, nBase, 32, KT, Nr, tid);
    CP_COMMIT();

    for (int s = 0; s < KSTEPS; ++s) {
        CP_WAIT1();
        __syncthreads();

        if (s + 2 < KSTEPS)
            prefetch_tiles(smbase + ((s + 2) % 3) * STAGE_B, Ahi, Alo, Bhi, Blo,
                           mBase, nBase, (s + 2) * 32, KT, Nr, tid);
        CP_COMMIT();

        uint32_t smA = smbase + (s % 3) * STAGE_B;
        uint32_t smB = smA + 2 * A_COMP;
#pragma unroll
        for (int ks = 0; ks < 2; ++ks) {
            // A fragments for all 4 m16 tiles, hi + lo
            uint32_t ah[4][4], al[4][4];
#pragma unroll
            for (int mi = 0; mi < 4; ++mi) {
                int ra = wr * 64 + mi * 16 + (lane & 15);
                int cl = ks * 2 + (lane >> 4);
                uint32_t off = ra * 64 + (((cl + (ra >> 1)) & 3) << 4);
                LDSM_X4(ah[mi][0], ah[mi][1], ah[mi][2], ah[mi][3], smA + off);
                LDSM_X4(al[mi][0], al[mi][1], al[mi][2], al[mi][3], smA + A_COMP + off);
            }
#pragma unroll
            for (int p = 0; p < 4; ++p) {
                int rn = wc * 64 + p * 16 + ((lane >> 4) & 1) * 8 + (lane & 7);
                int cl = ks * 2 + ((lane >> 3) & 1);
                uint32_t off = rn * 64 + (((cl + (rn >> 1)) & 3) << 4);
                uint32_t bh[2][2], bl[2][2];
                LDSM_X4(bh[0][0], bh[0][1], bh[1][0], bh[1][1], smB + off);
                LDSM_X4(bl[0][0], bl[0][1], bl[1][0], bl[1][1], smB + B_COMP + off);
#pragma unroll
                for (int mi = 0; mi < 4; ++mi) {
#pragma unroll
                    for (int q = 0; q < 2; ++q) {
                        int ni = 2 * p + q;
                        MMA16816(acc[mi][ni], ah[mi], bh[q]);
                        MMA16816(acc[mi][ni], al[mi], bh[q]);
                        MMA16816(acc[mi][ni], ah[mi], bl[q]);
                    }
                }
            }
        }
    }

    // ---------------- epilogue ----------------
    int rbase = mBase + wr * 64 + (lane >> 2);
    int cbase = nBase + wc * 64 + (lane & 3) * 2;

    if (EPI == 0) {
        int sIdx = nBase >> 12;
#pragma unroll
        for (int mi = 0; mi < 4; ++mi) {
#pragma unroll
            for (int h = 0; h < 2; ++h) {
                int row = rbase + mi * 16 + h * 8;
                float rs = 0.0f;
#pragma unroll
                for (int ni = 0; ni < 8; ++ni) {
                    int n = cbase + ni * 8;
                    float2 bz = *(const float2*)&biasv[n];
                    float v0 = acc[mi][ni][2 * h] + bz.x;
                    float v1 = acc[mi][ni][2 * h + 1] + bz.y;
                    float g0 = expf(-v0 * v0);
                    float g1 = expf(-v1 * v1);
                    *(float2*)&g_act[(size_t)row * N1 + n] = make_float2(g0, g1);
                    rs += g0 * g0 + g1 * g1;
                }
                rs += __shfl_xor_sync(0xffffffffu, rs, 1);
                rs += __shfl_xor_sync(0xffffffffu, rs, 2);
                if ((lane & 3) == 0) atomicAdd(&g_norm[row * Sq + sIdx], rs);
            }
        }
    } else if (EPI == 1) {
#pragma unroll
        for (int mi = 0; mi < 4; ++mi) {
#pragma unroll
            for (int h = 0; h < 2; ++h) {
                int row = rbase + mi * 16 + h * 8;
#pragma unroll
                for (int ni = 0; ni < 8; ++ni) {
                    int n = cbase + ni * 8;
                    float2 bz = *(const float2*)&biasv[n];
                    float v0 = acc[mi][ni][2 * h] + bz.x;
                    float v1 = acc[mi][ni][2 * h + 1] + bz.y;
                    float g0 = 1.0f / (1.0f + expf(-v0));
                    float g1 = 1.0f / (1.0f + expf(-v1));
                    size_t idx = (size_t)row * Hq + n;
                    float2 sr = *(float2*)&g_supr[idx];
                    float2 si = *(float2*)&g_supi[idx];
                    sr.x *= g0; sr.y *= g1; si.x *= g0; si.y *= g1;
                    *(float2*)&g_supr[idx] = sr;
                    *(float2*)&g_supi[idx] = si;
                }
            }
        }
    } else {
#pragma unroll
        for (int mi = 0; mi < 4; ++mi) {
#pragma unroll
            for (int h = 0; h < 2; ++h) {
                int row = rbase + mi * 16 + h * 8;
#pragma unroll
                for (int ni = 0; ni < 8; ++ni) {
                    int n = cbase + ni * 8;
                    if (n < Nr) {
                        float2 bz = *(const float2*)&biasv[n];
                        float v0 = acc[mi][ni][2 * h] + bz.x;
                        float v1 = acc[mi][ni][2 * h + 1] + bz.y;
                        *(float2*)&outp[(size_t)row * Cq + n] = make_float2(v0, v1);
                    }
                }
            }
        }
    }
}

// ---------------- superposition: phase mix + normalize ---------------------
__global__ __launch_bounds__(256) void sup_kernel() {
    int idx = blockIdx.x * blockDim.x + threadIdx.x;
    int b = idx >> 11, h = idx & (Hq - 1);
    float r = 0.0f, im = 0.0f;
#pragma unroll
    for (int s = 0; s < Sq; s++) {
        float f  = rsqrtf(g_norm[b * Sq + s] + EPSq);
        float a  = g_act[(size_t)b * N1 + s * (2 * Hq) + h];
        float be = g_act[(size_t)b * N1 + s * (2 * Hq) + Hq + h];
        float c  = g_cphi[s * Hq + h];
        float sp = g_sphi[s * Hq + h];
        r  += f * (a * c - be * sp);
        im += f * (a * sp + be * c);
    }
    g_supr[idx] = r;
    g_supi[idx] = im;
    float m = sqrtf(r * r + im * im);
    __half mh = __float2half_rn(m);
    g_mhi[idx] = mh;
    g_mlo[idx] = __float2half_rn(m - __half2float(mh));
}

// mag hi/lo regeneration between gate steps (separate kernel -> no race)
__global__ __launch_bounds__(256) void mag_split_kernel() {
    int idx = blockIdx.x * blockDim.x + threadIdx.x;
    float r = g_supr[idx], im = g_supi[idx];
    float m = sqrtf(r * r + im * im);
    __half mh = __float2half_rn(m);
    g_mhi[idx] = mh;
    g_mlo[idx] = __float2half_rn(m - __half2float(mh));
}

// ---------------- exact top-k (k=256 of 2048), msq fused --------------------
__global__ __launch_bounds__(256) void topk_kernel() {
    __shared__ float sv[Hq];
    __shared__ int swarp[8];
    __shared__ float fwarp[8];
    __shared__ int scnt;
    __shared__ float ssum;

    int b = blockIdx.x;
    int t = threadIdx.x;
    for (int i = t; i < Hq; i += 256) {
        float r = g_supr[(size_t)b * Hq + i];
        float im = g_supi[(size_t)b * Hq + i];
        sv[i] = r * r + im * im;
    }
    __syncthreads();

    unsigned thr = 0u;
    for (int bit = 30; bit >= 0; --bit) {
        unsigned cand = thr | (1u << bit);
        int c = 0;
        for (int i = t; i < Hq; i += 256)
            c += (__float_as_uint(sv[i]) >= cand) ? 1 : 0;
#pragma unroll
        for (int o = 16; o; o >>= 1) c += __shfl_down_sync(0xffffffffu, c, o);
        if ((t & 31) == 0) swarp[t >> 5] = c;
        __syncthreads();
        if (t < 32) {
            int cc = (t < 8) ? swarp[t] : 0;
#pragma unroll
            for (int o = 4; o; o >>= 1) cc += __shfl_down_sync(0xffffffffu, cc, o);
            if (t == 0) scnt = cc;
        }
        __syncthreads();
        if (scnt >= TOPKq) thr = cand;
        __syncthreads();
    }
    float T = __uint_as_float(thr);

    {
        int c = 0;
        for (int i = t; i < Hq; i += 256) c += (sv[i] > T) ? 1 : 0;
#pragma unroll
        for (int o = 16; o; o >>= 1) c += __shfl_down_sync(0xffffffffu, c, o);
        if ((t & 31) == 0) swarp[t >> 5] = c;
        __syncthreads();
        if (t < 32) {
            int cc = (t < 8) ? swarp[t] : 0;
#pragma unroll
            for (int o = 4; o; o >>= 1) cc += __shfl_down_sync(0xffffffffu, cc, o);
            if (t == 0) scnt = cc;
        }
        __syncthreads();
    }
    int need_eq = TOPKq - scnt;
    __syncthreads();

    float vals[8];
    bool keep[8];
    float mysum = 0.0f;
#pragma unroll
    for (int l = 0; l < 8; l++) {
        int i = t + l * 256;
        float v = sv[i];
        bool k;
        if (v > T) k = true;
        else if (v == T) {
            int r = 0;
            for (int j = 0; j < i; j++) r += (sv[j] == T) ? 1 : 0;
            k = (r < need_eq);
        } else k = false;
        vals[l] = v;
        keep[l] = k;
        if (k) mysum += v;
    }
#pragma unroll
    for (int o = 16; o; o >>= 1) mysum += __shfl_down_sync(0xffffffffu, mysum, o);
    if ((t & 31) == 0) fwarp[t >> 5] = mysum;
    __syncthreads();
    if (t < 32) {
        float ss = (t < 8) ? fwarp[t] : 0.0f;
#pragma unroll
        for (int o = 4; o; o >>= 1) ss += __shfl_down_sync(0xffffffffu, ss, o);
        if (t == 0) ssum = ss;
    }
    __syncthreads();
    float denom = ssum + EPSq;
#pragma unroll
    for (int l = 0; l < 8; l++) {
        int i = t + l * 256;
        float p = keep[l] ? vals[l] / denom : 0.0f;
        __half h = __float2half_rn(p);
        g_pbhi[(size_t)b * Hq + i] = h;
        g_pblo[(size_t)b * Hq + i] = __float2half_rn(p - __half2float(h));
    }
}

// ---------------- launch ----------------------------------------------------
extern "C" void kernel_launch(void* const* d_in, const int* in_sizes, int n_in,
                              void* d_out, int out_size)
{
    const float* x      = (const float*)d_in[0];
    const float* W      = (const float*)d_in[1];
    const float* bias   = (const float*)d_in[2];
    const float* phases = (const float*)d_in[3];
    const float* gate_W = (const float*)d_in[4];
    const float* gate_b = (const float*)d_in[5];
    const float* clf_W  = (const float*)d_in[6];
    const float* clf_b  = (const float*)d_in[7];
    float* out = (float*)d_out;

    cudaFuncSetAttribute(mma_gemm_kernel<Iq, 0>,
                         cudaFuncAttributeMaxDynamicSharedMemorySize, GEMM_SMEM);
    cudaFuncSetAttribute(mma_gemm_kernel<Hq, 1>,
                         cudaFuncAttributeMaxDynamicSharedMemorySize, GEMM_SMEM);
    cudaFuncSetAttribute(mma_gemm_kernel<Hq, 2>,
                         cudaFuncAttributeMaxDynamicSharedMemorySize, GEMM_SMEM);

    __half *xhi, *xlo, *whi, *wlo, *gwhi, *gwlo, *cwhi, *cwlo;
    __half *mhi, *mlo, *pbhi, *pblo;
    cudaGetSymbolAddress((void**)&xhi, g_xhi);
    cudaGetSymbolAddress((void**)&xlo, g_xlo);
    cudaGetSymbolAddress((void**)&whi, g_whi);
    cudaGetSymbolAddress((void**)&wlo, g_wlo);
    cudaGetSymbolAddress((void**)&gwhi, g_gwhi);
    cudaGetSymbolAddress((void**)&gwlo, g_gwlo);
    cudaGetSymbolAddress((void**)&cwhi, g_cwhi);
    cudaGetSymbolAddress((void**)&cwlo, g_cwlo);
    cudaGetSymbolAddress((void**)&mhi, g_mhi);
    cudaGetSymbolAddress((void**)&mlo, g_mlo);
    cudaGetSymbolAddress((void**)&pbhi, g_pbhi);
    cudaGetSymbolAddress((void**)&pblo, g_pblo);

    zero_norm_kernel<<<(Bq * Sq + 255) / 256, 256>>>();
    sincos_kernel<<<(Sq * Hq + 255) / 256, 256>>>(phases);

    split_kernel<<<((Bq * Iq / 4) + 255) / 256, 256>>>(x, xhi, xlo, Bq * Iq / 4);
    split_kernel<<<(((size_t)N1 * Iq / 4) + 255) / 256, 256>>>(W, whi, wlo, N1 * Iq / 4);
    split_kernel<<<((Hq * Hq / 4) + 255) / 256, 256>>>(gate_W, gwhi, gwlo, Hq * Hq / 4);
    split_kernel<<<((Cq * Hq / 4) + 255) / 256, 256>>>(clf_W, cwhi, cwlo, Cq * Hq / 4);

    // GEMM1: act = exp(-(x @ W^T + b)^2), fp16 3-term emulation
    mma_gemm_kernel<Iq, 0><<<dim3(Bq / 128, N1 / 256), 256, GEMM_SMEM>>>(
        xhi, xlo, whi, wlo, bias, nullptr, N1);

    // sup + first mag split fused
    sup_kernel<<<(Bq * Hq) / 256, 256>>>();

    // gate step 0
    mma_gemm_kernel<Hq, 1><<<dim3(Bq / 128, Hq / 256), 256, GEMM_SMEM>>>(
        mhi, mlo, gwhi, gwlo, gate_b, nullptr, Hq);
    // regenerate mag between steps
    mag_split_kernel<<<(Bq * Hq) / 256, 256>>>();
    // gate step 1
    mma_gemm_kernel<Hq, 1><<<dim3(Bq / 128, Hq / 256), 256, GEMM_SMEM>>>(
        mhi, mlo, gwhi, gwlo, gate_b, nullptr, Hq);

    topk_kernel<<<Bq, 256>>>();

    mma_gemm_kernel<Hq, 2><<<dim3(Bq / 128, (Cq + 255) / 256), 256, GEMM_SMEM>>>(
        pbhi, pblo, cwhi, cwlo, clf_b, out, Cq);
}

// round 9
// speedup vs baseline: 1.0925x; 1.0925x over previous
#include <cuda_runtime.h>
#include <cuda_fp16.h>
#include <math.h>
#include <stdint.h>

// Problem constants
#define Bq 2048
#define Iq 1024
#define Hq 2048
#define Cq 1000
#define Sq 8
#define N1 (Sq * 2 * Hq)   // 32768
#define TOPKq 256
#define EPSq 1e-8f

// ---------------- scratch (device globals; no allocation allowed) ----------
__device__ float g_act[(size_t)Bq * N1];
__device__ float g_norm[Bq * Sq];
__device__ float g_cphi[Sq * Hq];
__device__ float g_sphi[Sq * Hq];
__device__ float g_supr[Bq * Hq];
__device__ float g_supi[Bq * Hq];

// fp16 hi/lo splits (both operands) for near-fp32 emulation
__device__ __align__(16) __half g_xhi[(size_t)Bq * Iq];
__device__ __align__(16) __half g_xlo[(size_t)Bq * Iq];
__device__ __align__(16) __half g_whi[(size_t)N1 * Iq];
__device__ __align__(16) __half g_wlo[(size_t)N1 * Iq];
__device__ __align__(16) __half g_gwhi[(size_t)Hq * Hq];
__device__ __align__(16) __half g_gwlo[(size_t)Hq * Hq];
__device__ __align__(16) __half g_cwhi[(size_t)Cq * Hq];
__device__ __align__(16) __half g_cwlo[(size_t)Cq * Hq];
__device__ __align__(16) __half g_mhi[(size_t)Bq * Hq];    // mag before gate 0
__device__ __align__(16) __half g_mlo[(size_t)Bq * Hq];
__device__ __align__(16) __half g_m2hi[(size_t)Bq * Hq];   // mag before gate 1
__device__ __align__(16) __half g_m2lo[(size_t)Bq * Hq];
__device__ __align__(16) __half g_pbhi[(size_t)Bq * Hq];
__device__ __align__(16) __half g_pblo[(size_t)Bq * Hq];

// ---------------- PTX helpers ----------------------------------------------
__device__ __forceinline__ uint32_t smem_u32(const void* p) {
    uint32_t a;
    asm("{ .reg .u64 t; cvta.to.shared.u64 t, %1; cvt.u32.u64 %0, t; }" : "=r"(a) : "l"(p));
    return a;
}

#define CP16(dst, src, szr) \
    asm volatile("cp.async.cg.shared.global [%0], [%1], 16, %2;" \
                 :: "r"(dst), "l"(src), "r"(szr) : "memory")
#define CP_COMMIT() asm volatile("cp.async.commit_group;" ::: "memory")
#define CP_WAIT1()  asm volatile("cp.async.wait_group 1;" ::: "memory")

#define LDSM_X4(r0, r1, r2, r3, addr) \
    asm volatile("ldmatrix.sync.aligned.m8n8.x4.shared.b16 {%0,%1,%2,%3}, [%4];" \
                 : "=r"(r0), "=r"(r1), "=r"(r2), "=r"(r3) : "r"(addr))

#define MMA16816(d, a, b) \
    asm volatile("mma.sync.aligned.m16n8k16.row.col.f32.f16.f16.f32 " \
                 "{%0,%1,%2,%3}, {%4,%5,%6,%7}, {%8,%9}, {%0,%1,%2,%3};" \
                 : "+f"((d)[0]), "+f"((d)[1]), "+f"((d)[2]), "+f"((d)[3]) \
                 : "r"((a)[0]), "r"((a)[1]), "r"((a)[2]), "r"((a)[3]), \
                   "r"((b)[0]), "r"((b)[1]))

// ---------------- small helpers --------------------------------------------
__global__ void zero_norm_kernel() {
    int i = blockIdx.x * blockDim.x + threadIdx.x;
    if (i < Bq * Sq) g_norm[i] = 0.0f;
}

__global__ void sincos_kernel(const float* __restrict__ phases) {
    int i = blockIdx.x * blockDim.x + threadIdx.x;
    if (i < Sq * Hq) {
        float s, c;
        sincosf(phases[i], &s, &c);
        g_cphi[i] = c;
        g_sphi[i] = s;
    }
}

// fp32 -> fp16 hi/lo split
__global__ __launch_bounds__(256) void split_kernel(
    const float* __restrict__ src, __half* __restrict__ hi,
    __half* __restrict__ lo, int n4)
{
    int i = blockIdx.x * blockDim.x + threadIdx.x;
    if (i >= n4) return;
    float4 v = ((const float4*)src)[i];
    __half h0 = __float2half_rn(v.x);
    __half h1 = __float2half_rn(v.y);
    __half h2 = __float2half_rn(v.z);
    __half h3 = __float2half_rn(v.w);
    __half2 hh0 = {h0, h1}, hh1 = {h2, h3};
    ((__half2*)hi)[i * 2 + 0] = hh0;
    ((__half2*)hi)[i * 2 + 1] = hh1;
    __half2 ll0 = {__float2half_rn(v.x - __half2float(h0)),
                   __float2half_rn(v.y - __half2float(h1))};
    __half2 ll1 = {__float2half_rn(v.z - __half2float(h2)),
                   __float2half_rn(v.w - __half2float(h3))};
    ((__half2*)lo)[i * 2 + 0] = ll0;
    ((__half2*)lo)[i * 2 + 1] = ll1;
}

// ---------------- unified warp-mma GEMM (fp16 3-term) ------------------------
// CTA tile 128x128, 256 threads (8 warps, 2x4), warp tile 64x32.
// K-step 32, cp.async 3-stage pipeline. EPI: 0=gemm1, 1=gate, 2=clf.
#define CTILE 8192   // bytes per smem component (128 rows * 64 B)
#define GEMM_SMEM (3 * 4 * CTILE)   // 96 KB -> 2 CTAs/SM

__device__ __forceinline__ void prefetch_tiles(
    uint32_t smb, const __half* __restrict__ Ahi, const __half* __restrict__ Alo,
    const __half* __restrict__ Bhi, const __half* __restrict__ Blo,
    int mBase, int nBase, int kk, int KT, int Nr, int tid)
{
#pragma unroll
    for (int l = 0; l < 2; ++l) {
        int idx = tid + l * 256;
        int r = idx >> 2, c = idx & 3;
        uint32_t dst = smb + r * 64 + (((c + (r >> 1)) & 3) << 4);
        size_t ka = (size_t)(mBase + r) * KT + kk + c * 8;
        size_t kb = (size_t)(nBase + r) * KT + kk + c * 8;
        int bsz = ((nBase + r) < Nr) ? 16 : 0;
        CP16(dst,              Ahi + ka, 16);
        CP16(dst + CTILE,      Alo + ka, 16);
        CP16(dst + 2 * CTILE,  Bhi + kb, bsz);
        CP16(dst + 3 * CTILE,  Blo + kb, bsz);
    }
}

template <int KT, int EPI>
__global__ __launch_bounds__(256, 2) void mma_gemm_kernel(
    const __half* __restrict__ Ahi, const __half* __restrict__ Alo,
    const __half* __restrict__ Bhi, const __half* __restrict__ Blo,
    const float* __restrict__ biasv, float* __restrict__ outp,
    __half* __restrict__ mout_hi, __half* __restrict__ mout_lo, int Nr)
{
    extern __shared__ __align__(16) char dynsm[];
    uint32_t smbase = smem_u32(dynsm);
    const int STAGE = 4 * CTILE;

    int tid = threadIdx.x;
    int lane = tid & 31, wid = tid >> 5;
    int wr = wid >> 2, wc = wid & 3;
    int mBase = blockIdx.x * 128;
    int nBase = blockIdx.y * 128;

    float acc[4][4][4];
#pragma unroll
    for (int a = 0; a < 4; a++)
#pragma unroll
        for (int b = 0; b < 4; b++)
#pragma unroll
            for (int c = 0; c < 4; c++) acc[a][b][c] = 0.0f;

    const int KSTEPS = KT / 32;
    prefetch_tiles(smbase, Ahi, Alo, Bhi, Blo, mBase, nBase, 0, KT, Nr, tid);
    CP_COMMIT();
    prefetch_tiles(smbase + STAGE, Ahi, Alo, Bhi, Blo, mBase, nBase, 32, KT, Nr, tid);
    CP_COMMIT();

    for (int s = 0; s < KSTEPS; ++s) {
        CP_WAIT1();
        __syncthreads();

        if (s + 2 < KSTEPS)
            prefetch_tiles(smbase + ((s + 2) % 3) * STAGE, Ahi, Alo, Bhi, Blo,
                           mBase, nBase, (s + 2) * 32, KT, Nr, tid);
        CP_COMMIT();

        uint32_t smA = smbase + (s % 3) * STAGE;
        uint32_t smB = smA + 2 * CTILE;
#pragma unroll
        for (int ks = 0; ks < 2; ++ks) {
            uint32_t bh[4][2], bl[4][2];
#pragma unroll
            for (int p = 0; p < 2; ++p) {
                int rn = wc * 32 + p * 16 + ((lane >> 4) & 1) * 8 + (lane & 7);
                int cl = ks * 2 + ((lane >> 3) & 1);
                uint32_t off = rn * 64 + (((cl + (rn >> 1)) & 3) << 4);
                LDSM_X4(bh[2 * p][0], bh[2 * p][1], bh[2 * p + 1][0], bh[2 * p + 1][1], smB + off);
                LDSM_X4(bl[2 * p][0], bl[2 * p][1], bl[2 * p + 1][0], bl[2 * p + 1][1],
                        smB + CTILE + off);
            }
#pragma unroll
            for (int mi = 0; mi < 4; ++mi) {
                int ra = wr * 64 + mi * 16 + (lane & 15);
                int cl = ks * 2 + (lane >> 4);
                uint32_t off = ra * 64 + (((cl + (ra >> 1)) & 3) << 4);
                uint32_t ah[4], al[4];
                LDSM_X4(ah[0], ah[1], ah[2], ah[3], smA + off);
                LDSM_X4(al[0], al[1], al[2], al[3], smA + CTILE + off);
#pragma unroll
                for (int ni = 0; ni < 4; ++ni) {
                    MMA16816(acc[mi][ni], ah, bh[ni]);
                    MMA16816(acc[mi][ni], al, bh[ni]);
                    MMA16816(acc[mi][ni], ah, bl[ni]);
                }
            }
        }
    }

    // ---------------- epilogue ----------------
    int rbase = mBase + wr * 64 + (lane >> 2);
    int cbase = nBase + wc * 32 + (lane & 3) * 2;

    if (EPI == 0) {
        int sIdx = nBase >> 12;
#pragma unroll
        for (int mi = 0; mi < 4; ++mi) {
#pragma unroll
            for (int h = 0; h < 2; ++h) {
                int row = rbase + mi * 16 + h * 8;
                float rs = 0.0f;
#pragma unroll
                for (int ni = 0; ni < 4; ++ni) {
                    int n = cbase + ni * 8;
                    float2 bz = *(const float2*)&biasv[n];
                    float v0 = acc[mi][ni][2 * h] + bz.x;
                    float v1 = acc[mi][ni][2 * h + 1] + bz.y;
                    float g0 = expf(-v0 * v0);
                    float g1 = expf(-v1 * v1);
                    *(float2*)&g_act[(size_t)row * N1 + n] = make_float2(g0, g1);
                    rs += g0 * g0 + g1 * g1;
                }
                rs += __shfl_xor_sync(0xffffffffu, rs, 1);
                rs += __shfl_xor_sync(0xffffffffu, rs, 2);
                if ((lane & 3) == 0) atomicAdd(&g_norm[row * Sq + sIdx], rs);
            }
        }
    } else if (EPI == 1) {
        // gate: RMW supr/supi; optionally emit next-step mag into a DIFFERENT
        // buffer pair (mout). No kernel reads mout before the next launch ->
        // no cross-CTA race (round-5 lesson: never write a buffer other CTAs
        // of the same launch are reading).
#pragma unroll
        for (int mi = 0; mi < 4; ++mi) {
#pragma unroll
            for (int h = 0; h < 2; ++h) {
                int row = rbase + mi * 16 + h * 8;
#pragma unroll
                for (int ni = 0; ni < 4; ++ni) {
                    int n = cbase + ni * 8;
                    float2 bz = *(const float2*)&biasv[n];
                    float v0 = acc[mi][ni][2 * h] + bz.x;
                    float v1 = acc[mi][ni][2 * h + 1] + bz.y;
                    float g0 = 1.0f / (1.0f + expf(-v0));
                    float g1 = 1.0f / (1.0f + expf(-v1));
                    size_t idx = (size_t)row * Hq + n;
                    float2 sr = *(float2*)&g_supr[idx];
                    float2 si = *(float2*)&g_supi[idx];
                    sr.x *= g0; sr.y *= g1; si.x *= g0; si.y *= g1;
                    *(float2*)&g_supr[idx] = sr;
                    *(float2*)&g_supi[idx] = si;
                    if (mout_hi) {
                        float m0 = sqrtf(sr.x * sr.x + si.x * si.x);
                        float m1 = sqrtf(sr.y * sr.y + si.y * si.y);
                        __half mh0 = __float2half_rn(m0);
                        __half mh1 = __float2half_rn(m1);
                        *(__half2*)&mout_hi[idx] = __half2{mh0, mh1};
                        *(__half2*)&mout_lo[idx] = __half2{
                            __float2half_rn(m0 - __half2float(mh0)),
                            __float2half_rn(m1 - __half2float(mh1))};
                    }
                }
            }
        }
    } else {
#pragma unroll
        for (int mi = 0; mi < 4; ++mi) {
#pragma unroll
            for (int h = 0; h < 2; ++h) {
                int row = rbase + mi * 16 + h * 8;
#pragma unroll
                for (int ni = 0; ni < 4; ++ni) {
                    int n = cbase + ni * 8;
                    if (n < Nr) {
                        float2 bz = *(const float2*)&biasv[n];
                        float v0 = acc[mi][ni][2 * h] + bz.x;
                        float v1 = acc[mi][ni][2 * h + 1] + bz.y;
                        *(float2*)&outp[(size_t)row * Cq + n] = make_float2(v0, v1);
                    }
                }
            }
        }
    }
}

// ---------------- superposition: phase mix + normalize ---------------------
__global__ __launch_bounds__(256) void sup_kernel() {
    int idx = blockIdx.x * blockDim.x + threadIdx.x;
    int b = idx >> 11, h = idx & (Hq - 1);
    float r = 0.0f, im = 0.0f;
#pragma unroll
    for (int s = 0; s < Sq; s++) {
        float f  = rsqrtf(g_norm[b * Sq + s] + EPSq);
        float a  = g_act[(size_t)b * N1 + s * (2 * Hq) + h];
        float be = g_act[(size_t)b * N1 + s * (2 * Hq) + Hq + h];
        float c  = g_cphi[s * Hq + h];
        float sp = g_sphi[s * Hq + h];
        r  += f * (a * c - be * sp);
        im += f * (a * sp + be * c);
    }
    g_supr[idx] = r;
    g_supi[idx] = im;
    float m = sqrtf(r * r + im * im);
    __half mh = __float2half_rn(m);
    g_mhi[idx] = mh;
    g_mlo[idx] = __float2half_rn(m - __half2float(mh));
}

// ---------------- exact top-k (k=256 of 2048), msq fused --------------------
__global__ __launch_bounds__(256) void topk_kernel() {
    __shared__ float sv[Hq];
    __shared__ int swarp[8];
    __shared__ float fwarp[8];
    __shared__ int scnt;
    __shared__ float ssum;

    int b = blockIdx.x;
    int t = threadIdx.x;
    for (int i = t; i < Hq; i += 256) {
        float r = g_supr[(size_t)b * Hq + i];
        float im = g_supi[(size_t)b * Hq + i];
        sv[i] = r * r + im * im;
    }
    __syncthreads();

    unsigned thr = 0u;
    for (int bit = 30; bit >= 0; --bit) {
        unsigned cand = thr | (1u << bit);
        int c = 0;
        for (int i = t; i < Hq; i += 256)
            c += (__float_as_uint(sv[i]) >= cand) ? 1 : 0;
#pragma unroll
        for (int o = 16; o; o >>= 1) c += __shfl_down_sync(0xffffffffu, c, o);
        if ((t & 31) == 0) swarp[t >> 5] = c;
        __syncthreads();
        if (t < 32) {
            int cc = (t < 8) ? swarp[t] : 0;
#pragma unroll
            for (int o = 4; o; o >>= 1) cc += __shfl_down_sync(0xffffffffu, cc, o);
            if (t == 0) scnt = cc;
        }
        __syncthreads();
        if (scnt >= TOPKq) thr = cand;
        __syncthreads();
    }
    float T = __uint_as_float(thr);

    {
        int c = 0;
        for (int i = t; i < Hq; i += 256) c += (sv[i] > T) ? 1 : 0;
#pragma unroll
        for (int o = 16; o; o >>= 1) c += __shfl_down_sync(0xffffffffu, c, o);
        if ((t & 31) == 0) swarp[t >> 5] = c;
        __syncthreads();
        if (t < 32) {
            int cc = (t < 8) ? swarp[t] : 0;
#pragma unroll
            for (int o = 4; o; o >>= 1) cc += __shfl_down_sync(0xffffffffu, cc, o);
            if (t == 0) scnt = cc;
        }
        __syncthreads();
    }
    int need_eq = TOPKq - scnt;
    __syncthreads();

    float vals[8];
    bool keep[8];
    float mysum = 0.0f;
#pragma unroll
    for (int l = 0; l < 8; l++) {
        int i = t + l * 256;
        float v = sv[i];
        bool k;
        if (v > T) k = true;
        else if (v == T) {
            int r = 0;
            for (int j = 0; j < i; j++) r += (sv[j] == T) ? 1 : 0;
            k = (r < need_eq);
        } else k = false;
        vals[l] = v;
        keep[l] = k;
        if (k) mysum += v;
    }
#pragma unroll
    for (int o = 16; o; o >>= 1) mysum += __shfl_down_sync(0xffffffffu, mysum, o);
    if ((t & 31) == 0) fwarp[t >> 5] = mysum;
    __syncthreads();
    if (t < 32) {
        float ss = (t < 8) ? fwarp[t] : 0.0f;
#pragma unroll
        for (int o = 4; o; o >>= 1) ss += __shfl_down_sync(0xffffffffu, ss, o);
        if (t == 0) ssum = ss;
    }
    __syncthreads();
    float denom = ssum + EPSq;
#pragma unroll
    for (int l = 0; l < 8; l++) {
        int i = t + l * 256;
        float p = keep[l] ? vals[l] / denom : 0.0f;
        __half h = __float2half_rn(p);
        g_pbhi[(size_t)b * Hq + i] = h;
        g_pblo[(size_t)b * Hq + i] = __float2half_rn(p - __half2float(h));
    }
}

// ---------------- launch ----------------------------------------------------
extern "C" void kernel_launch(void* const* d_in, const int* in_sizes, int n_in,
                              void* d_out, int out_size)
{
    const float* x      = (const float*)d_in[0];
    const float* W      = (const float*)d_in[1];
    const float* bias   = (const float*)d_in[2];
    const float* phases = (const float*)d_in[3];
    const float* gate_W = (const float*)d_in[4];
    const float* gate_b = (const float*)d_in[5];
    const float* clf_W  = (const float*)d_in[6];
    const float* clf_b  = (const float*)d_in[7];
    float* out = (float*)d_out;

    cudaFuncSetAttribute(mma_gemm_kernel<Iq, 0>,
                         cudaFuncAttributeMaxDynamicSharedMemorySize, GEMM_SMEM);
    cudaFuncSetAttribute(mma_gemm_kernel<Hq, 1>,
                         cudaFuncAttributeMaxDynamicSharedMemorySize, GEMM_SMEM);
    cudaFuncSetAttribute(mma_gemm_kernel<Hq, 2>,
                         cudaFuncAttributeMaxDynamicSharedMemorySize, GEMM_SMEM);

    __half *xhi, *xlo, *whi, *wlo, *gwhi, *gwlo, *cwhi, *cwlo;
    __half *mhi, *mlo, *m2hi, *m2lo, *pbhi, *pblo;
    cudaGetSymbolAddress((void**)&xhi, g_xhi);
    cudaGetSymbolAddress((void**)&xlo, g_xlo);
    cudaGetSymbolAddress((void**)&whi, g_whi);
    cudaGetSymbolAddress((void**)&wlo, g_wlo);
    cudaGetSymbolAddress((void**)&gwhi, g_gwhi);
    cudaGetSymbolAddress((void**)&gwlo, g_gwlo);
    cudaGetSymbolAddress((void**)&cwhi, g_cwhi);
    cudaGetSymbolAddress((void**)&cwlo, g_cwlo);
    cudaGetSymbolAddress((void**)&mhi, g_mhi);
    cudaGetSymbolAddress((void**)&mlo, g_mlo);
    cudaGetSymbolAddress((void**)&m2hi, g_m2hi);
    cudaGetSymbolAddress((void**)&m2lo, g_m2lo);
    cudaGetSymbolAddress((void**)&pbhi, g_pbhi);
    cudaGetSymbolAddress((void**)&pblo, g_pblo);

    // Launch order arranged so ncu (-s 5 -c 1) captures GEMM1 (launch #6).
    zero_norm_kernel<<<(Bq * Sq + 255) / 256, 256>>>();                       // 1
    sincos_kernel<<<(Sq * Hq + 255) / 256, 256>>>(phases);                    // 2
    split_kernel<<<((Bq * Iq / 4) + 255) / 256, 256>>>(x, xhi, xlo,
                                                       Bq * Iq / 4);          // 3
    split_kernel<<<(((size_t)N1 * Iq / 4) + 255) / 256, 256>>>(W, whi, wlo,
                                                               N1 * Iq / 4);  // 4
    split_kernel<<<((Hq * Hq / 4) + 255) / 256, 256>>>(gate_W, gwhi, gwlo,
                                                       Hq * Hq / 4);          // 5

    // GEMM1: act = exp(-(x @ W^T + b)^2), fp16 3-term emulation            // 6
    mma_gemm_kernel<Iq, 0><<<dim3(Bq / 128, N1 / 128), 256, GEMM_SMEM>>>(
        xhi, xlo, whi, wlo, bias, nullptr, nullptr, nullptr, N1);

    split_kernel<<<((Cq * Hq / 4) + 255) / 256, 256>>>(clf_W, cwhi, cwlo,
                                                       Cq * Hq / 4);          // 7

    // sup + first mag split fused                                           // 8
    sup_kernel<<<(Bq * Hq) / 256, 256>>>();

    // gate step 0: reads mhi/mlo, emits m2hi/m2lo (distinct buffers)        // 9
    mma_gemm_kernel<Hq, 1><<<dim3(Bq / 128, Hq / 128), 256, GEMM_SMEM>>>(
        mhi, mlo, gwhi, gwlo, gate_b, nullptr, m2hi, m2lo, Hq);
    // gate step 1: reads m2hi/m2lo, no mag output                           // 10
    mma_gemm_kernel<Hq, 1><<<dim3(Bq / 128, Hq / 128), 256, GEMM_SMEM>>>(
        m2hi, m2lo, gwhi, gwlo, gate_b, nullptr, nullptr, nullptr, Hq);

    topk_kernel<<<Bq, 256>>>();                                               // 11

    mma_gemm_kernel<Hq, 2><<<dim3(Bq / 128, (Cq + 127) / 128), 256, GEMM_SMEM>>>(
        pbhi, pblo, cwhi, cwlo, clf_b, out, nullptr, nullptr, Cq);            // 12
}